// round 16
// baseline (speedup 1.0000x reference)
#include <cuda_runtime.h>
#include <cuda_fp16.h>
#include <math.h>
#include <cstdint>

// Problem constants
#define BB 2
#define TT 2048
#define DD 2048
#define HH 16
#define KK 8
#define HD 128
#define MTOT (BB*TT)   // 4096

// ---------------------------------------------------------------------------
// Scratch (device globals; no allocation allowed)
// ---------------------------------------------------------------------------
__device__ __half g_xhi [(size_t)MTOT * DD];
__device__ __half g_wqt [(size_t)(HH*HD) * DD];
__device__ __half g_wkt [(size_t)(KK*HD) * DD];
__device__ __half g_wvt [(size_t)(KK*HD) * DD];
__device__ __half g_wot [(size_t)DD * (HH*HD)];
__device__ __half g_qhi [(size_t)MTOT * (HH*HD)];
__device__ __half g_khi [(size_t)MTOT * (KK*HD)];
__device__ __half g_vhi [(size_t)MTOT * (KK*HD)];
__device__ __half g_ohi [(size_t)MTOT * (HH*HD)];

// 1/sqrt(128) * log2(e)  — folded into Q so flash can use exp2
#define QSCALE (0.08838834764831845f * 1.4426950408889634f)

// ---------------------------------------------------------------------------
// mma.sync / cp.async helpers
// ---------------------------------------------------------------------------
__device__ __forceinline__ uint32_t smem_to_u32(const void* p) {
    uint32_t a;
    asm("{ .reg .u64 t; cvta.to.shared.u64 t, %1; cvt.u32.u64 %0, t; }"
        : "=r"(a) : "l"(p));
    return a;
}

__device__ __forceinline__ uint32_t h2_as_u32(__half2 h) {
    uint32_t u;
    memcpy(&u, &h, 4);
    return u;
}

__device__ __forceinline__ void ldsm_x4(uint32_t& r0, uint32_t& r1,
                                        uint32_t& r2, uint32_t& r3, uint32_t addr) {
    asm volatile("ldmatrix.sync.aligned.m8n8.x4.shared.b16 {%0,%1,%2,%3}, [%4];"
                 : "=r"(r0), "=r"(r1), "=r"(r2), "=r"(r3) : "r"(addr));
}

__device__ __forceinline__ void ldsm_x4_trans(uint32_t& r0, uint32_t& r1,
                                              uint32_t& r2, uint32_t& r3, uint32_t addr) {
    asm volatile("ldmatrix.sync.aligned.m8n8.x4.trans.shared.b16 {%0,%1,%2,%3}, [%4];"
                 : "=r"(r0), "=r"(r1), "=r"(r2), "=r"(r3) : "r"(addr));
}

__device__ __forceinline__ void mma_f16(float* d, const uint32_t* a,
                                        uint32_t b0, uint32_t b1) {
    asm volatile(
        "mma.sync.aligned.m16n8k16.row.col.f32.f16.f16.f32 "
        "{%0,%1,%2,%3}, {%4,%5,%6,%7}, {%8,%9}, {%0,%1,%2,%3};"
        : "+f"(d[0]), "+f"(d[1]), "+f"(d[2]), "+f"(d[3])
        : "r"(a[0]), "r"(a[1]), "r"(a[2]), "r"(a[3]), "r"(b0), "r"(b1));
}

__device__ __forceinline__ void cp_async16(uint32_t saddr, const void* gaddr) {
    asm volatile("cp.async.cg.shared.global [%0], [%1], 16;"
                 :: "r"(saddr), "l"(gaddr) : "memory");
}
__device__ __forceinline__ void cp_commit() {
    asm volatile("cp.async.commit_group;" ::: "memory");
}

// ---------------------------------------------------------------------------
// Fused prep: convert x to fp16 + transpose all 4 weights (coalesced writes).
// ---------------------------------------------------------------------------
__device__ __forceinline__ void transpose_body(const float* __restrict__ W,
                                               __half* __restrict__ T,
                                               int Kd, int N, int n0, int k0) {
    __shared__ float ts[32][129];
    int lane = threadIdx.x & 31, w = threadIdx.x >> 5;
#pragma unroll
    for (int i = 0; i < 16; ++i) {
        int k = w * 16 + i;
        ts[lane][k] = W[(size_t)(k0 + k) * N + n0 + lane];
    }
    __syncthreads();
#pragma unroll
    for (int j = 0; j < 4; ++j) {
        int n = w * 4 + j;
        float f0 = ts[n][4*lane], f1 = ts[n][4*lane+1];
        float f2 = ts[n][4*lane+2], f3 = ts[n][4*lane+3];
        __half2* dst = (__half2*)(T + (size_t)(n0 + n) * Kd + k0 + 4 * lane);
        dst[0] = __halves2half2(__float2half_rn(f0), __float2half_rn(f1));
        dst[1] = __halves2half2(__float2half_rn(f2), __float2half_rn(f3));
    }
}

__global__ __launch_bounds__(256)
void prep_kernel(const float* __restrict__ x,
                 const float* __restrict__ Wq, const float* __restrict__ Wk,
                 const float* __restrict__ Wv, const float* __restrict__ Wo,
                 __half* __restrict__ Xh, __half* __restrict__ Tq,
                 __half* __restrict__ Tk, __half* __restrict__ Tv,
                 __half* __restrict__ To) {
    int bid = blockIdx.x;
    if (bid < 8192) {
        int i = bid * 256 + threadIdx.x;
        float4 v = ((const float4*)x)[i];
        __half2* hp = (__half2*)(Xh + 4 * (size_t)i);
        hp[0] = __halves2half2(__float2half_rn(v.x), __float2half_rn(v.y));
        hp[1] = __halves2half2(__float2half_rn(v.z), __float2half_rn(v.w));
    } else if (bid < 9216) {
        int l = bid - 8192;                       // Wq: 64 n x 16 k
        transpose_body(Wq, Tq, DD, HH*HD, (l & 63) * 32, (l >> 6) * 128);
    } else if (bid < 9728) {
        int l = bid - 9216;                       // Wk: 32 x 16
        transpose_body(Wk, Tk, DD, KK*HD, (l & 31) * 32, (l >> 5) * 128);
    } else if (bid < 10240) {
        int l = bid - 9728;                       // Wv: 32 x 16
        transpose_body(Wv, Tv, DD, KK*HD, (l & 31) * 32, (l >> 5) * 128);
    } else {
        int l = bid - 10240;                      // Wo: 64 x 16
        transpose_body(Wo, To, HH*HD, HH*HD, (l & 63) * 32, (l >> 6) * 128);
    }
}

// ---------------------------------------------------------------------------
// Pure fp16 GEMM, K-chunk 64, 2-stage double buffer, ONE barrier per chunk.
// mode 0: fp32 out ; mode 1: fp16 out ; mode 2: fused RMSNorm+RoPE epilogue.
// ---------------------------------------------------------------------------
#define GPADH 72
#define GTILE_BYTES (128 * GPADH * 2)       // 18432
#define GSTAGE_BYTES (2 * GTILE_BYTES)      // 36864
#define GSMEM_DYN (2 * GSTAGE_BYTES)        // 73728 -> 2 CTAs/SM

__device__ __forceinline__ void gemm_core(
    const __half* __restrict__ A, const __half* __restrict__ B,
    float* __restrict__ C, __half* __restrict__ Ch,
    int N, int Kd, int row0, int col0, char* smg, int mode,
    const float* __restrict__ nw, const float* __restrict__ sinp,
    const float* __restrict__ cosp, float oscale) {
    const uint32_t sbase0 = smem_to_u32(smg);

    const int tid = threadIdx.x;
    const int lane = tid & 31;
    const int wid = tid >> 5;
    const int wr = wid & 3;
    const int wc = wid >> 2;

    float d[2][8][4];
#pragma unroll
    for (int m = 0; m < 2; ++m)
#pragma unroll
        for (int n = 0; n < 8; ++n)
#pragma unroll
            for (int j = 0; j < 4; ++j) d[m][n][j] = 0.0f;

    const int lrow = tid >> 3;
    const int lseg = tid & 7;

    auto cp_chunk = [&](int k0, int stage) {
        uint32_t st = sbase0 + stage * GSTAGE_BYTES;
#pragma unroll
        for (int j = 0; j < 4; ++j) {
            int r = lrow + j * 32;
            uint32_t so = r * (GPADH * 2) + lseg * 16;
            cp_async16(st + so,
                       A + (size_t)(row0 + r) * Kd + k0 + lseg * 8);
            cp_async16(st + GTILE_BYTES + so,
                       B + (size_t)(col0 + r) * Kd + k0 + lseg * 8);
        }
        cp_commit();
    };

    const int NC = Kd / 64;

    cp_chunk(0, 0);

    for (int c = 0; c < NC; ++c) {
        asm volatile("cp.async.wait_group 0;" ::: "memory");
        __syncthreads();
        if (c + 1 < NC) cp_chunk((c + 1) * 64, (c + 1) & 1);

        const uint32_t sb = sbase0 + (c & 1) * GSTAGE_BYTES;
#pragma unroll
        for (int ks = 0; ks < 4; ++ks) {
            const uint32_t coff = ks * 32 + (lane >> 4) * 16;
            uint32_t ah[2][4];
#pragma unroll
            for (int mb = 0; mb < 2; ++mb) {
                uint32_t addr = sb + (wr * 32 + mb * 16 + (lane & 15)) * (GPADH*2) + coff;
                ldsm_x4(ah[mb][0], ah[mb][1], ah[mb][2], ah[mb][3], addr);
            }
            uint32_t bh[4][4];
#pragma unroll
            for (int nb = 0; nb < 4; ++nb) {
                uint32_t addr = sb + GTILE_BYTES +
                                (wc * 64 + nb * 16 + (lane & 15)) * (GPADH*2) + coff;
                ldsm_x4(bh[nb][0], bh[nb][1], bh[nb][2], bh[nb][3], addr);
            }
#pragma unroll
            for (int mb = 0; mb < 2; ++mb) {
#pragma unroll
                for (int nb = 0; nb < 4; ++nb) {
                    mma_f16(d[mb][2*nb],   ah[mb], bh[nb][0], bh[nb][2]);
                    mma_f16(d[mb][2*nb+1], ah[mb], bh[nb][1], bh[nb][3]);
                }
            }
        }
    }

    const int frow = lane >> 2;
    const int fcol = 2 * (lane & 3);

    if (mode == 2) {
        __syncthreads();
        __half* stg = (__half*)smg;
        const int SSTR = 132;
#pragma unroll
        for (int mb = 0; mb < 2; ++mb) {
#pragma unroll
            for (int nt = 0; nt < 8; ++nt) {
                int r = wr * 32 + mb * 16 + frow;
                int cc = wc * 64 + nt * 8 + fcol;
                *(__half2*)&stg[r * SSTR + cc] =
                    __halves2half2(__float2half_rn(d[mb][nt][0]), __float2half_rn(d[mb][nt][1]));
                *(__half2*)&stg[(r + 8) * SSTR + cc] =
                    __halves2half2(__float2half_rn(d[mb][nt][2]), __float2half_rn(d[mb][nt][3]));
            }
        }
        __syncthreads();

        float w0 = nw[2 * lane],      w1 = nw[2 * lane + 1];
        float w2 = nw[64 + 2 * lane], w3 = nw[65 + 2 * lane];
#pragma unroll 4
        for (int i = 0; i < 16; ++i) {
            int r = wid * 16 + i;
            int grow_t = row0 + r;
            int t = grow_t & (TT - 1);
            __half2 a2 = *(__half2*)&stg[r * SSTR + 2 * lane];
            __half2 c2 = *(__half2*)&stg[r * SSTR + 64 + 2 * lane];
            float ax = __low2float(a2), ay = __high2float(a2);
            float bx = __low2float(c2), by = __high2float(c2);

            float ss = ax * ax + ay * ay + bx * bx + by * by;
#pragma unroll
            for (int o = 16; o; o >>= 1) ss += __shfl_xor_sync(0xFFFFFFFFu, ss, o);
            float rinv = rsqrtf(ss * (1.0f / 128.0f) + 1e-6f);

            float n0 = ax * rinv * w0, n1 = ay * rinv * w1;
            float n2 = bx * rinv * w2, n3 = by * rinv * w3;

            float s0 = sinp[t * 64 + lane],      c0 = cosp[t * 64 + lane];
            float s1 = sinp[t * 64 + lane + 32], c1 = cosp[t * 64 + lane + 32];
            float o0 = (n0 * c0 - n1 * s0) * oscale;
            float o1 = (n2 * c1 - n3 * s1) * oscale;
            float o2 = (n0 * s0 + n1 * c0) * oscale;
            float o3 = (n2 * s1 + n3 * c1) * oscale;

            __half* ptr = Ch + (size_t)grow_t * N + col0;
            ptr[lane]      = __float2half_rn(o0);
            ptr[lane + 32] = __float2half_rn(o1);
            ptr[lane + 64] = __float2half_rn(o2);
            ptr[lane + 96] = __float2half_rn(o3);
        }
        return;
    }

#pragma unroll
    for (int mb = 0; mb < 2; ++mb) {
#pragma unroll
        for (int nt = 0; nt < 8; ++nt) {
            int r = row0 + wr * 32 + mb * 16 + frow;
            int cc = col0 + wc * 64 + nt * 8 + fcol;
            if (mode == 1) {
                *(__half2*)&Ch[(size_t)r * N + cc] =
                    __halves2half2(__float2half_rn(d[mb][nt][0]), __float2half_rn(d[mb][nt][1]));
                *(__half2*)&Ch[(size_t)(r + 8) * N + cc] =
                    __halves2half2(__float2half_rn(d[mb][nt][2]), __float2half_rn(d[mb][nt][3]));
            } else {
                *(float2*)&C[(size_t)r * N + cc]       = make_float2(d[mb][nt][0], d[mb][nt][1]);
                *(float2*)&C[(size_t)(r + 8) * N + cc] = make_float2(d[mb][nt][2], d[mb][nt][3]);
            }
        }
    }
}

__global__ __launch_bounds__(256, 2)
void gemm_mma(const __half* __restrict__ A, const __half* __restrict__ B,
              float* __restrict__ C, int N, int Kd) {
    extern __shared__ char smg[];
    gemm_core(A, B, C, nullptr, N, Kd, blockIdx.y * 128, blockIdx.x * 128, smg,
              0, nullptr, nullptr, nullptr, 1.0f);
}

__global__ __launch_bounds__(256, 2)
void gemm_qkv(const __half* __restrict__ Xhi,
              const __half* __restrict__ Wq, const __half* __restrict__ Wk,
              const __half* __restrict__ Wv,
              __half* __restrict__ Qh, __half* __restrict__ Kh, __half* __restrict__ Vh,
              const float* __restrict__ qn, const float* __restrict__ kn,
              const float* __restrict__ sinp, const float* __restrict__ cosp) {
    extern __shared__ char smg[];
    int ct = blockIdx.x;
    if (ct < 16) {
        gemm_core(Xhi, Wq, nullptr, Qh, HH*HD, DD, blockIdx.y * 128, ct * 128, smg,
                  2, qn, sinp, cosp, QSCALE);
    } else if (ct < 24) {
        gemm_core(Xhi, Wk, nullptr, Kh, KK*HD, DD, blockIdx.y * 128, (ct - 16) * 128, smg,
                  2, kn, sinp, cosp, 1.0f);
    } else {
        gemm_core(Xhi, Wv, nullptr, Vh, KK*HD, DD, blockIdx.y * 128, (ct - 24) * 128, smg,
                  1, nullptr, nullptr, nullptr, 1.0f);
    }
}

// ---------------------------------------------------------------------------
// Flash attention: pure-fp16 mma, fp16 packed exp2 softmax (fp32 max/sum),
// packed P directly reused as PV fragments. 128-row Q tile, 8 warps x 16
// rows, double-buffered K/V, ONE barrier per K-tile, 2 CTAs/SM.
// ---------------------------------------------------------------------------
#define FK_STRB 272
#define FQ_TILE (128 * FK_STRB)
#define FKV_TILE (64 * FK_STRB)
#define F4_Q 0
#define F4_KV FQ_TILE
#define FA5_SMEM (FQ_TILE + 2 * 2 * FKV_TILE)   // 104448 -> 2 CTAs/SM

__global__ __launch_bounds__(256, 2)
void flash_mma(const __half* __restrict__ Qhi,
               const __half* __restrict__ Khi, const __half* __restrict__ Vhi,
               __half* __restrict__ Ohi) {
    extern __shared__ char sm[];
    const uint32_t sb = smem_to_u32(sm);

    const int qt = gridDim.x - 1 - blockIdx.x;
    const int bh = blockIdx.y;
    const int b = bh >> 4;
    const int h = bh & 15;
    const int kh = h >> 1;

    const int tid = threadIdx.x;
    const int lane = tid & 31;
    const int wid = tid >> 5;
    const int frow = lane >> 2;
    const int fcol = 2 * (lane & 3);

    const int qrow0 = qt * 128 + wid * 16;
    const int ktmax = 2 * qt + 1;

    const __half* qh = Qhi + ((size_t)(b * TT + qt * 128)) * (HH*HD) + h * HD;
    const __half* kbase = Khi + ((size_t)(b * TT)) * (KK*HD) + kh * HD;
    const __half* vbase = Vhi + ((size_t)(b * TT)) * (KK*HD) + kh * HD;

    auto cp_kv = [&](int kt, int stage) {
        uint32_t st = sb + F4_KV + stage * 2 * FKV_TILE;
        const __half* kp = kbase + (size_t)(kt * 64) * (KK*HD);
        const __half* vp = vbase + (size_t)(kt * 64) * (KK*HD);
#pragma unroll
        for (int j = 0; j < 4; ++j) {
            int idx = tid + j * 256;
            int r = idx >> 4, s = idx & 15;
            uint32_t so = r * FK_STRB + s * 16;
            cp_async16(st + so,            kp + (size_t)r * (KK*HD) + s * 8);
            cp_async16(st + FKV_TILE + so, vp + (size_t)r * (KK*HD) + s * 8);
        }
        cp_commit();
    };

    {
#pragma unroll
        for (int j = 0; j < 8; ++j) {
            int idx = tid + j * 256;
            int r = idx >> 4, s = idx & 15;
            cp_async16(sb + F4_Q + r * FK_STRB + s * 16,
                       qh + (size_t)r * (HH*HD) + s * 8);
        }
        cp_commit();
        cp_kv(0, 0);
    }

    float o[16][4];
#pragma unroll
    for (int n = 0; n < 16; ++n)
#pragma unroll
        for (int j = 0; j < 4; ++j) o[n][j] = 0.0f;
    float m0 = -INFINITY, m1 = -INFINITY, l0 = 0.0f, l1 = 0.0f;

    for (int kt = 0; kt <= ktmax; ++kt) {
        asm volatile("cp.async.wait_group 0;" ::: "memory");
        __syncthreads();
        if (kt < ktmax) cp_kv(kt + 1, (kt + 1) & 1);

        const uint32_t kvs = sb + F4_KV + (kt & 1) * 2 * FKV_TILE;

        // ---- S = Q @ K^T (Q pre-scaled, exp2 units) ----
        float s[8][4];
#pragma unroll
        for (int i = 0; i < 8; ++i)
#pragma unroll
            for (int j = 0; j < 4; ++j) s[i][j] = 0.0f;

#pragma unroll
        for (int ks = 0; ks < 8; ++ks) {
            const uint32_t coff = ks * 32 + (lane >> 4) * 16;
            uint32_t aq[4];
            {
                uint32_t addr = sb + F4_Q + (wid * 16 + (lane & 15)) * FK_STRB + coff;
                ldsm_x4(aq[0], aq[1], aq[2], aq[3], addr);
            }
            uint32_t kb[4][4];
#pragma unroll
            for (int nb = 0; nb < 4; ++nb) {
                uint32_t addr = kvs + (nb * 16 + (lane & 15)) * FK_STRB + coff;
                ldsm_x4(kb[nb][0], kb[nb][1], kb[nb][2], kb[nb][3], addr);
            }
#pragma unroll
            for (int nb = 0; nb < 4; ++nb) {
                mma_f16(s[2*nb],   aq, kb[nb][0], kb[nb][2]);
                mma_f16(s[2*nb+1], aq, kb[nb][1], kb[nb][3]);
            }
        }

        // ---- causal mask ----
        bool boundary = (kt * 64 + 63 > qrow0);
        if (boundary) {
#pragma unroll
            for (int nt = 0; nt < 8; ++nt) {
                int c = kt * 64 + nt * 8 + fcol;
                int r0 = qrow0 + frow, r1 = r0 + 8;
                if (c     > r0) s[nt][0] = -INFINITY;
                if (c + 1 > r0) s[nt][1] = -INFINITY;
                if (c     > r1) s[nt][2] = -INFINITY;
                if (c + 1 > r1) s[nt][3] = -INFINITY;
            }
        }

        // ---- online softmax: fp32 max, fp16 packed exp2, fp32 sum ----
        float mx0 = -INFINITY, mx1 = -INFINITY;
#pragma unroll
        for (int nt = 0; nt < 8; ++nt) {
            mx0 = fmaxf(mx0, fmaxf(s[nt][0], s[nt][1]));
            mx1 = fmaxf(mx1, fmaxf(s[nt][2], s[nt][3]));
        }
        mx0 = fmaxf(mx0, __shfl_xor_sync(0xFFFFFFFFu, mx0, 1));
        mx0 = fmaxf(mx0, __shfl_xor_sync(0xFFFFFFFFu, mx0, 2));
        mx1 = fmaxf(mx1, __shfl_xor_sync(0xFFFFFFFFu, mx1, 1));
        mx1 = fmaxf(mx1, __shfl_xor_sync(0xFFFFFFFFu, mx1, 2));
        mx0 = fmaxf(mx0, m0);
        mx1 = fmaxf(mx1, m1);
        float a0 = exp2f(m0 - mx0);
        float a1 = exp2f(m1 - mx1);
        float sum0 = 0.0f, sum1 = 0.0f;
        uint32_t pp0[8], pp1[8];     // packed P: rows (frow, frow+8) pairs
#pragma unroll
        for (int nt = 0; nt < 8; ++nt) {
            __half2 p01 = h2exp2(__floats2half2_rn(s[nt][0] - mx0, s[nt][1] - mx0));
            __half2 p23 = h2exp2(__floats2half2_rn(s[nt][2] - mx1, s[nt][3] - mx1));
            pp0[nt] = h2_as_u32(p01);
            pp1[nt] = h2_as_u32(p23);
            float2 f01 = __half22float2(p01);
            float2 f23 = __half22float2(p23);
            sum0 += f01.x + f01.y;
            sum1 += f23.x + f23.y;
        }
        sum0 += __shfl_xor_sync(0xFFFFFFFFu, sum0, 1);
        sum0 += __shfl_xor_sync(0xFFFFFFFFu, sum0, 2);
        sum1 += __shfl_xor_sync(0xFFFFFFFFu, sum1, 1);
        sum1 += __shfl_xor_sync(0xFFFFFFFFu, sum1, 2);
        l0 = l0 * a0 + sum0;  m0 = mx0;
        l1 = l1 * a1 + sum1;  m1 = mx1;

#pragma unroll
        for (int nt = 0; nt < 16; ++nt) {
            o[nt][0] *= a0; o[nt][1] *= a0;
            o[nt][2] *= a1; o[nt][3] *= a1;
        }

        // ---- O += P @ V ; packed P registers ARE the A-fragments ----
#pragma unroll
        for (int j = 0; j < 4; ++j) {
            uint32_t ap[4];
            ap[0] = pp0[2*j];
            ap[1] = pp1[2*j];
            ap[2] = pp0[2*j+1];
            ap[3] = pp1[2*j+1];
#pragma unroll
            for (int g = 0; g < 2; ++g) {
                uint32_t vh[4][4];
#pragma unroll
                for (int q = 0; q < 4; ++q) {
                    int nb = g * 4 + q;
                    uint32_t addr = kvs + FKV_TILE
                                  + (j * 16 + (lane & 15)) * FK_STRB
                                  + (nb * 16 + (lane >> 4) * 8) * 2;
                    ldsm_x4_trans(vh[q][0], vh[q][1], vh[q][2], vh[q][3], addr);
                }
#pragma unroll
                for (int q = 0; q < 4; ++q) {
                    int nb = g * 4 + q;
                    mma_f16(o[2*nb],   ap, vh[q][0], vh[q][1]);
                    mma_f16(o[2*nb+1], ap, vh[q][2], vh[q][3]);
                }
            }
        }
    }

    // Epilogue
    {
        float li0 = 1.0f / l0;
        float li1 = 1.0f / l1;
        int r0g = b * TT + qt * 128 + wid * 16 + frow;
#pragma unroll
        for (int nt = 0; nt < 16; ++nt) {
            int c = nt * 8 + fcol;
            size_t o0 = (size_t)r0g * (HH*HD) + h * HD + c;
            size_t o1 = (size_t)(r0g + 8) * (HH*HD) + h * HD + c;
            *(__half2*)&Ohi[o0] = __halves2half2(__float2half_rn(o[nt][0] * li0),
                                                 __float2half_rn(o[nt][1] * li0));
            *(__half2*)&Ohi[o1] = __halves2half2(__float2half_rn(o[nt][2] * li1),
                                                 __float2half_rn(o[nt][3] * li1));
        }
    }
}

// ---------------------------------------------------------------------------
extern "C" void kernel_launch(void* const* d_in, const int* in_sizes, int n_in,
                              void* d_out, int out_size) {
    const float* x    = (const float*)d_in[0];
    const float* Wq   = (const float*)d_in[1];
    const float* Wk   = (const float*)d_in[2];
    const float* Wv   = (const float*)d_in[3];
    const float* Wo   = (const float*)d_in[4];
    const float* qn   = (const float*)d_in[5];
    const float* kn   = (const float*)d_in[6];
    const float* sinp = (const float*)d_in[7];
    const float* cosp = (const float*)d_in[8];
    float* out = (float*)d_out;

    __half *xhi, *wqt, *wkt, *wvt, *wot;
    __half *qhi, *khi, *vhi, *ohi;
    cudaGetSymbolAddress((void**)&xhi, g_xhi);
    cudaGetSymbolAddress((void**)&wqt, g_wqt);
    cudaGetSymbolAddress((void**)&wkt, g_wkt);
    cudaGetSymbolAddress((void**)&wvt, g_wvt);
    cudaGetSymbolAddress((void**)&wot, g_wot);
    cudaGetSymbolAddress((void**)&qhi, g_qhi);
    cudaGetSymbolAddress((void**)&khi, g_khi);
    cudaGetSymbolAddress((void**)&vhi, g_vhi);
    cudaGetSymbolAddress((void**)&ohi, g_ohi);

    // 1. fused prep
    prep_kernel<<<11264, 256>>>(x, Wq, Wk, Wv, Wo, xhi, wqt, wkt, wvt, wot);

    // 2. fused QKV projection + RMSNorm/RoPE epilogue
    cudaFuncSetAttribute(gemm_qkv, cudaFuncAttributeMaxDynamicSharedMemorySize, GSMEM_DYN);
    gemm_qkv<<<dim3(32, MTOT/128), 256, GSMEM_DYN>>>(xhi, wqt, wkt, wvt,
                                                     qhi, khi, vhi,
                                                     qn, kn, sinp, cosp);

    // 3. causal flash attention (fp16 packed exp2 softmax)
    cudaFuncSetAttribute(flash_mma, cudaFuncAttributeMaxDynamicSharedMemorySize, FA5_SMEM);
    flash_mma<<<dim3(TT / 128, BB * HH), 256, FA5_SMEM>>>(qhi, khi, vhi, ohi);

    // 4. output projection
    cudaFuncSetAttribute(gemm_mma, cudaFuncAttributeMaxDynamicSharedMemorySize, GSMEM_DYN);
    gemm_mma<<<dim3((HH*HD)/128, MTOT/128), 256, GSMEM_DYN>>>(ohi, wot, out, HH*HD, HH*HD);
}